// round 10
// baseline (speedup 1.0000x reference)
#include <cuda_runtime.h>
#include <cuda_bf16.h>
#include <cstdint>

#define BATCH 4
#define NN    4096
#define DIM   64
#define NROWS (BATCH * NN)   // 16384
#define PAIRROWS (2 * NN)    // 8192 rows per batch-pair

#define STAGES   7
#define KT_TOT   (NN / 64)           // 64 K-chunks of 64
#define ROWB     144                 // 72 bf16 padded row = 144 B (conflict-free ldmatrix)
#define A_STG    (64 * ROWB)         // 9216 B
#define B_STG    (64 * ROWB)         // 9216 B
#define STG      (A_STG + B_STG)     // 18432 B

// ---------------- device scratch (static; no cudaMalloc) ----------------
__device__ __align__(16) __nv_bfloat16 g_A[(size_t)BATCH * NN * NN];   // bf16 (g+I)
__device__ __align__(16) float         g_deg[NROWS];
__device__ __align__(16) float         g_P[4][(size_t)NROWS * DIM];    // P_k = x @ W_k^T
__device__ __align__(16) __nv_bfloat16 g_sbf[2][(size_t)NROWS * DIM];  // ping-pong bf16 state T = D*S

// ---------------- asm helpers (base-ISA only; compute_103-safe) ----------------
__device__ __forceinline__ void cp_async16_s(uint32_t dst, const void* src) {
    asm volatile("cp.async.cg.shared.global [%0], [%1], 16;\n" :: "r"(dst), "l"(src));
}
__device__ __forceinline__ void mbar_init(uint32_t a, uint32_t cnt) {
    asm volatile("mbarrier.init.shared.b64 [%0], %1;\n" :: "r"(a), "r"(cnt) : "memory");
}
__device__ __forceinline__ void mbar_arrive(uint32_t a) {
    asm volatile("mbarrier.arrive.shared.b64 _, [%0];\n" :: "r"(a) : "memory");
}
__device__ __forceinline__ void cp_arrive_noinc(uint32_t a) {
    asm volatile("cp.async.mbarrier.arrive.noinc.shared.b64 [%0];\n" :: "r"(a) : "memory");
}
__device__ __forceinline__ void mbar_wait(uint32_t a, uint32_t parity) {
    asm volatile(
        "{\n\t.reg .pred P1;\n\t"
        "WAIT_%=:\n\t"
        "mbarrier.try_wait.parity.acquire.cta.shared::cta.b64 P1, [%0], %1, 0x989680;\n\t"
        "@P1 bra.uni DONE_%=;\n\t"
        "bra.uni WAIT_%=;\n\t"
        "DONE_%=:\n\t}"
        :: "r"(a), "r"(parity) : "memory");
}

// ---------------- kernel 1: fused degree + bf16(g+I), single pass, per batch-pair ----------------
__global__ void __launch_bounds__(256) prep_kernel(const float* __restrict__ graph, int pair) {
    int row  = pair * PAIRROWS + blockIdx.x * 8 + (threadIdx.x >> 5);
    int lane = threadIdx.x & 31;
    int il   = row & (NN - 1);
    const float4* p = reinterpret_cast<const float4*>(graph + (size_t)row * NN);
    __nv_bfloat16* dst = g_A + (size_t)row * NN;

    float s = 0.f;
    #pragma unroll 4
    for (int i = lane; i < NN / 8; i += 32) {
        float4 v0 = p[2 * i];
        float4 v1 = p[2 * i + 1];
        int j0 = i * 8;
        int dsl = il - j0;
        if (dsl >= 0 && dsl < 8) {                       // self loop
            float* vv = (dsl < 4) ? reinterpret_cast<float*>(&v0) : reinterpret_cast<float*>(&v1);
            vv[dsl & 3] += 1.f;
        }
        s += ((v0.x + v0.y) + (v0.z + v0.w)) + ((v1.x + v1.y) + (v1.z + v1.w));
        __nv_bfloat16 o[8] = {__float2bfloat16(v0.x), __float2bfloat16(v0.y),
                              __float2bfloat16(v0.z), __float2bfloat16(v0.w),
                              __float2bfloat16(v1.x), __float2bfloat16(v1.y),
                              __float2bfloat16(v1.z), __float2bfloat16(v1.w)};
        *reinterpret_cast<uint4*>(dst + j0) = *reinterpret_cast<uint4*>(o);
    }
    #pragma unroll
    for (int o = 16; o; o >>= 1) s += __shfl_xor_sync(0xffffffffu, s, o);
    if (lane == 0) g_deg[row] = 1.f / (sqrtf(s) + 1e-7f);
}

// ---------------- kernel 2: P_k = x @ W_k^T, seed T0 = bf16(d * P3), per batch-pair ----------------
__global__ void __launch_bounds__(256) precompute_kernel(const float* __restrict__ x,
                                                         const float* __restrict__ W, int pair) {
    __shared__ float xs[64][65];
    const int tid  = threadIdx.x;
    const int d    = tid & 63;
    const int kseg = tid >> 6;
    const int row0 = pair * PAIRROWS + blockIdx.x * 64;

    float wreg[64];
    const float4* wp = (const float4*)(W + d * 256 + kseg * 64);
    #pragma unroll
    for (int i = 0; i < 16; i++) {
        float4 v = wp[i];
        wreg[i*4+0] = v.x; wreg[i*4+1] = v.y; wreg[i*4+2] = v.z; wreg[i*4+3] = v.w;
    }
    for (int idx = tid; idx < 64 * 64; idx += 256) {
        int r = idx >> 6, c = idx & 63;
        xs[r][c] = x[(size_t)(row0 + r) * DIM + c];
    }
    __syncthreads();

    for (int r = 0; r < 64; r++) {
        float a0 = 0.f, a1 = 0.f;
        #pragma unroll
        for (int c = 0; c < 64; c += 2) {
            a0 += xs[r][c]     * wreg[c];
            a1 += xs[r][c + 1] * wreg[c + 1];
        }
        float acc = a0 + a1;
        size_t gi = (size_t)(row0 + r) * DIM + d;
        g_P[kseg][gi] = acc;
        if (kseg == 3) g_sbf[0][gi] = __float2bfloat16(acc * g_deg[row0 + r]);
    }
}

// ---------------- kernel 3: warp-specialized mma.sync GEMM, per batch-pair ----------------
// CTA tile 64x64, grid (64, 2). Warps 0-3 consume (32x32 tiles); warps 4-7 produce
// (cp.async -> 7-stage ring; 129 KB smem -> 1 CTA/SM -> 128 CTAs on 128 SMs).
// A for the pair (64 MB) is L2-resident across all three steps.
__global__ void __launch_bounds__(256) gemm_kernel(const __nv_bfloat16* __restrict__ Tin,
                                                   __nv_bfloat16* __restrict__ Tout,
                                                   const float* __restrict__ Padd,
                                                   float* __restrict__ outp,   // null unless last step
                                                   const float* __restrict__ bias,
                                                   int bpair) {
    extern __shared__ char smem_raw[];
    const uint32_t base = (uint32_t)__cvta_generic_to_shared(smem_raw);
    const uint32_t barb = base + STAGES * STG;     // full[s] @ barb+16s, empty[s] @ barb+16s+8

    const int tid = threadIdx.x, lane = tid & 31, wid = tid >> 5;
    const size_t b = bpair * 2 + blockIdx.y;
    const int m0 = blockIdx.x * 64;

    const __nv_bfloat16* A = g_A + b * ((size_t)NN * NN) + (size_t)m0 * NN;
    const __nv_bfloat16* B = Tin + b * ((size_t)NN * DIM);

    if (tid == 0) {
        #pragma unroll
        for (int s = 0; s < STAGES; s++) {
            mbar_init(barb + 16 * s, 128);         // full: 128 producer threads (cp-completion arrives)
            mbar_init(barb + 16 * s + 8, 128);     // empty: 128 consumer threads
        }
    }
    __syncthreads();

    if (wid >= 4) {
        // ================= producers =================
        const int ptid = tid - 128;                // 0..127
        int st_i = 0, ph = 1;                      // empty-wait cursor (first pass free)
        for (int kt = 0; kt < KT_TOT; kt++) {
            mbar_wait(barb + 16 * st_i + 8, (uint32_t)ph);
            const uint32_t st = base + st_i * STG;
            const int kb = kt * 64;
            #pragma unroll
            for (int i = 0; i < 4; i++) {          // A: 512 chunks of 16B
                int idx = ptid + i * 128;
                int r = idx >> 3, c = idx & 7;
                cp_async16_s(st + r * ROWB + c * 16, A + (size_t)r * NN + kb + c * 8);
            }
            #pragma unroll
            for (int i = 0; i < 4; i++) {          // B: 512 chunks of 16B
                int idx = ptid + i * 128;
                int r = idx >> 3, c = idx & 7;
                cp_async16_s(st + A_STG + r * ROWB + c * 16, B + (size_t)(kb + r) * DIM + c * 8);
            }
            cp_arrive_noinc(barb + 16 * st_i);     // arrive full[s] when this thread's cp.asyncs land
            if (++st_i == STAGES) { st_i = 0; ph ^= 1; }
        }
        return;
    }

    // ================= consumers =================
    const int wm = wid & 1, wn = wid >> 1;
    const int la = lane & 15, lb = lane >> 4;

    float acc[2][4][4];
    #pragma unroll
    for (int i = 0; i < 2; i++)
        #pragma unroll
        for (int j = 0; j < 4; j++)
            #pragma unroll
            for (int q = 0; q < 4; q++) acc[i][j][q] = 0.f;

    int st_i = 0, ph = 0;
    for (int kt = 0; kt < KT_TOT; kt++) {
        mbar_wait(barb + 16 * st_i, (uint32_t)ph);     // acquire full[s]
        const uint32_t sa = base + st_i * STG;
        const uint32_t sbm = sa + A_STG;

        #pragma unroll
        for (int kk = 0; kk < 64; kk += 16) {
            uint32_t af[2][4];
            #pragma unroll
            for (int mt = 0; mt < 2; mt++) {
                uint32_t p = sa + (wm * 32 + mt * 16 + la) * ROWB + (kk + lb * 8) * 2;
                asm volatile("ldmatrix.sync.aligned.m8n8.x4.shared.b16 {%0,%1,%2,%3},[%4];\n"
                             : "=r"(af[mt][0]), "=r"(af[mt][1]), "=r"(af[mt][2]), "=r"(af[mt][3])
                             : "r"(p));
            }
            uint32_t bf_[2][4];
            #pragma unroll
            for (int nh = 0; nh < 2; nh++) {
                uint32_t p = sbm + (kk + la) * ROWB + (wn * 32 + nh * 16 + lb * 8) * 2;
                asm volatile("ldmatrix.sync.aligned.m8n8.x4.trans.shared.b16 {%0,%1,%2,%3},[%4];\n"
                             : "=r"(bf_[nh][0]), "=r"(bf_[nh][1]), "=r"(bf_[nh][2]), "=r"(bf_[nh][3])
                             : "r"(p));
            }
            #pragma unroll
            for (int mt = 0; mt < 2; mt++)
                #pragma unroll
                for (int nt = 0; nt < 4; nt++) {
                    uint32_t b0 = bf_[nt >> 1][(nt & 1) * 2];
                    uint32_t b1 = bf_[nt >> 1][(nt & 1) * 2 + 1];
                    float* c = acc[mt][nt];
                    asm volatile(
                        "mma.sync.aligned.m16n8k16.row.col.f32.bf16.bf16.f32 "
                        "{%0,%1,%2,%3},{%4,%5,%6,%7},{%8,%9},{%0,%1,%2,%3};\n"
                        : "+f"(c[0]), "+f"(c[1]), "+f"(c[2]), "+f"(c[3])
                        : "r"(af[mt][0]), "r"(af[mt][1]), "r"(af[mt][2]), "r"(af[mt][3]),
                          "r"(b0), "r"(b1));
                }
        }
        mbar_arrive(barb + 16 * st_i + 8);             // release empty[s]
        if (++st_i == STAGES) { st_i = 0; ph ^= 1; }
    }

    // epilogue: S_next[r] = d_r*acc + P[r]; state T_next = bf16(d_r * S_next)
    #pragma unroll
    for (int mt = 0; mt < 2; mt++) {
        const size_t gr0 = b * NN + m0 + wm * 32 + mt * 16 + (lane >> 2);
        const size_t gr1 = gr0 + 8;
        const float d0 = g_deg[gr0], d1 = g_deg[gr1];
        #pragma unroll
        for (int nt = 0; nt < 4; nt++) {
            int c = wn * 32 + nt * 8 + (lane & 3) * 2;
            float2 p0 = *(const float2*)(Padd + gr0 * DIM + c);
            float2 p1 = *(const float2*)(Padd + gr1 * DIM + c);
            float* ac = acc[mt][nt];
            float s00 = d0 * ac[0] + p0.x, s01 = d0 * ac[1] + p0.y;
            float s10 = d1 * ac[2] + p1.x, s11 = d1 * ac[3] + p1.y;
            if (outp) {
                float b0 = bias[c], b1 = bias[c + 1];
                *(float2*)(outp + gr0 * DIM + c) = make_float2(s00 + b0, s01 + b1);
                *(float2*)(outp + gr1 * DIM + c) = make_float2(s10 + b0, s11 + b1);
            } else {
                *(__nv_bfloat162*)(Tout + gr0 * DIM + c) = __floats2bfloat162_rn(d0 * s00, d0 * s01);
                *(__nv_bfloat162*)(Tout + gr1 * DIM + c) = __floats2bfloat162_rn(d1 * s10, d1 * s11);
            }
        }
    }
}

// ---------------- launch ----------------
extern "C" void kernel_launch(void* const* d_in, const int* in_sizes, int n_in,
                              void* d_out, int out_size) {
    const float* x     = (const float*)d_in[0];   // [4,4096,64]
    const float* graph = (const float*)d_in[1];   // [4,4096,4096]
    const float* W     = (const float*)d_in[2];   // [64,256]
    const float* bias  = (const float*)d_in[3];   // [64]
    float* out = (float*)d_out;                   // [4,4096,64]

    const int smem_bytes = STAGES * STG + STAGES * 16;    // 129024 + 112 -> 1 CTA/SM
    static bool attr_set = false;                 // persistent process state, not a work guard
    if (!attr_set) {
        cudaFuncSetAttribute(gemm_kernel, cudaFuncAttributeMaxDynamicSharedMemorySize, smem_bytes);
        attr_set = true;
    }

    __nv_bfloat16* s0 = nullptr;
    cudaGetSymbolAddress((void**)&s0, g_sbf);     // g_sbf[0]
    __nv_bfloat16* s1 = s0 + (size_t)NROWS * DIM; // g_sbf[1]
    float* P = nullptr;
    cudaGetSymbolAddress((void**)&P, g_P);        // g_P[0]

    dim3 grid(NN / 64, 2);                        // 128 CTAs per pair-step
    for (int pair = 0; pair < 2; pair++) {
        // phase-interleaved per batch-pair: A_pair (64 MB bf16) stays L2-resident
        // from the prep write through all three propagation steps.
        prep_kernel<<<PAIRROWS / 8, 256>>>(graph, pair);
        precompute_kernel<<<PAIRROWS / 64, 256>>>(x, W, pair);
        gemm_kernel<<<grid, 256, smem_bytes>>>(s0, s1, P + 2 * (size_t)NROWS * DIM, nullptr, bias, pair);
        gemm_kernel<<<grid, 256, smem_bytes>>>(s1, s0, P + 1 * (size_t)NROWS * DIM, nullptr, bias, pair);
        gemm_kernel<<<grid, 256, smem_bytes>>>(s0, s1, P, out, bias, pair);
    }
}

// round 13
// speedup vs baseline: 1.7423x; 1.7423x over previous
#include <cuda_runtime.h>
#include <cuda_bf16.h>
#include <cstdint>

#define BATCH 4
#define NN    4096
#define DIM   64
#define NROWS (BATCH * NN)   // 16384

#define STAGES   6
#define KT_TOT   (NN / 64)           // 64 K-chunks of 64
#define A_STG    8192                // 64x64 bf16 tile, swizzled, contiguous
#define B_STG    8192                // 64 k-rows x 64 bf16, swizzled, contiguous
#define STG      (A_STG + B_STG)     // 16384

// ---------------- device scratch (static; no cudaMalloc) ----------------
// A stored TILED: g_A[((b*64 + mtile)*64 + ktile)*4096 + lr*64 + swizzle(c, lr)]
__device__ __align__(16) __nv_bfloat16 g_A[(size_t)BATCH * NN * NN];
__device__ __align__(16) float         g_deg[NROWS];
__device__ __align__(16) float         g_P[4][(size_t)NROWS * DIM];    // P_k = x @ W_k^T
__device__ __align__(16) __nv_bfloat16 g_sbf[2][(size_t)NROWS * DIM];  // bf16 state T = D*S, row-swizzled

// ---------------- asm helpers (base-ISA / sm_90 base; compute_103-safe) ----------------
__device__ __forceinline__ void mbar_init(uint32_t a, uint32_t cnt) {
    asm volatile("mbarrier.init.shared.b64 [%0], %1;\n" :: "r"(a), "r"(cnt) : "memory");
}
__device__ __forceinline__ void mbar_arrive(uint32_t a) {
    asm volatile("mbarrier.arrive.shared.b64 _, [%0];\n" :: "r"(a) : "memory");
}
__device__ __forceinline__ void mbar_expect_tx(uint32_t a, uint32_t bytes) {
    asm volatile("mbarrier.arrive.expect_tx.shared.b64 _, [%0], %1;\n" :: "r"(a), "r"(bytes) : "memory");
}
__device__ __forceinline__ void bulk_ld(uint32_t dst, const void* src, uint32_t bytes, uint32_t mbar) {
    asm volatile("cp.async.bulk.shared::cluster.global.mbarrier::complete_tx::bytes [%0], [%1], %2, [%3];\n"
                 :: "r"(dst), "l"(src), "r"(bytes), "r"(mbar) : "memory");
}
__device__ __forceinline__ void mbar_wait(uint32_t a, uint32_t parity) {
    asm volatile(
        "{\n\t.reg .pred P1;\n\t"
        "WAIT_%=:\n\t"
        "mbarrier.try_wait.parity.acquire.cta.shared::cta.b64 P1, [%0], %1, 0x989680;\n\t"
        "@P1 bra.uni DONE_%=;\n\t"
        "bra.uni WAIT_%=;\n\t"
        "DONE_%=:\n\t}"
        :: "r"(a), "r"(parity) : "memory");
}

// swizzled element offset within a 64-elem (128 B) row: chunk = col/8 XOR (row&7)
__device__ __forceinline__ int swz(int row, int col) {
    return (((col >> 3) ^ (row & 7)) << 3) + (col & 7);
}

// ---------------- kernel 1: fused degree + bf16(g+I) -> TILED swizzled A ----------------
__global__ void __launch_bounds__(256) prep_kernel(const float* __restrict__ graph) {
    int row  = blockIdx.x * 8 + (threadIdx.x >> 5);
    int lane = threadIdx.x & 31;
    int il   = row & (NN - 1);
    int b    = row >> 12;
    int mt   = il >> 6, lr = il & 63;
    const float4* p = reinterpret_cast<const float4*>(graph + (size_t)row * NN);
    const size_t rowTileBase = (((size_t)b * 64 + mt) * 64) * 4096;   // + kt*4096
    const int rswz = lr & 7;

    float s = 0.f;
    #pragma unroll 4
    for (int i = lane; i < NN / 8; i += 32) {
        float4 v0 = p[2 * i];
        float4 v1 = p[2 * i + 1];
        int j0 = i * 8;
        int dsl = il - j0;
        if (dsl >= 0 && dsl < 8) {                       // self loop
            float* vv = (dsl < 4) ? reinterpret_cast<float*>(&v0) : reinterpret_cast<float*>(&v1);
            vv[dsl & 3] += 1.f;
        }
        s += ((v0.x + v0.y) + (v0.z + v0.w)) + ((v1.x + v1.y) + (v1.z + v1.w));
        __nv_bfloat16 o[8] = {__float2bfloat16(v0.x), __float2bfloat16(v0.y),
                              __float2bfloat16(v0.z), __float2bfloat16(v0.w),
                              __float2bfloat16(v1.x), __float2bfloat16(v1.y),
                              __float2bfloat16(v1.z), __float2bfloat16(v1.w)};
        int kt = j0 >> 6;
        int c  = (j0 >> 3) & 7;
        __nv_bfloat16* dst = g_A + rowTileBase + (size_t)kt * 4096 + lr * 64 + ((c ^ rswz) << 3);
        *reinterpret_cast<uint4*>(dst) = *reinterpret_cast<uint4*>(o);
    }
    #pragma unroll
    for (int o = 16; o; o >>= 1) s += __shfl_xor_sync(0xffffffffu, s, o);
    if (lane == 0) g_deg[row] = 1.f / (sqrtf(s) + 1e-7f);
}

// ---------------- kernel 2: P_k = x @ W_k^T, seed T0 = bf16(d*P3) (swizzled rows) ----------------
__global__ void __launch_bounds__(256) precompute_kernel(const float* __restrict__ x,
                                                         const float* __restrict__ W) {
    __shared__ float xs[64][65];
    const int tid  = threadIdx.x;
    const int d    = tid & 63;
    const int kseg = tid >> 6;
    const int row0 = blockIdx.x * 64;

    float wreg[64];
    const float4* wp = (const float4*)(W + d * 256 + kseg * 64);
    #pragma unroll
    for (int i = 0; i < 16; i++) {
        float4 v = wp[i];
        wreg[i*4+0] = v.x; wreg[i*4+1] = v.y; wreg[i*4+2] = v.z; wreg[i*4+3] = v.w;
    }
    for (int idx = tid; idx < 64 * 64; idx += 256) {
        int r = idx >> 6, c = idx & 63;
        xs[r][c] = x[(size_t)(row0 + r) * DIM + c];
    }
    __syncthreads();

    for (int r = 0; r < 64; r++) {
        float a0 = 0.f, a1 = 0.f;
        #pragma unroll
        for (int c = 0; c < 64; c += 2) {
            a0 += xs[r][c]     * wreg[c];
            a1 += xs[r][c + 1] * wreg[c + 1];
        }
        float acc = a0 + a1;
        int gr = row0 + r;
        g_P[kseg][(size_t)gr * DIM + d] = acc;
        if (kseg == 3)
            g_sbf[0][(size_t)gr * DIM + swz(gr, d)] = __float2bfloat16(acc * g_deg[gr]);
    }
}

// ---------------- kernel 3: bulk-fed warp-specialized mma.sync GEMM ----------------
// Block 160 thr: warps 0-3 consume (32x32 tiles); warp-4 lane 0 produces via
// cp.async.bulk (2 ops/stage, byte-tracked by mbarrier complete_tx).
__global__ void __launch_bounds__(160) gemm_kernel(const __nv_bfloat16* __restrict__ Tin,
                                                   __nv_bfloat16* __restrict__ Tout,
                                                   const float* __restrict__ Padd,
                                                   float* __restrict__ outp,   // null unless last step
                                                   const float* __restrict__ bias) {
    extern __shared__ char smem_raw[];
    const uint32_t base = (uint32_t)__cvta_generic_to_shared(smem_raw);
    const uint32_t barb = base + STAGES * STG;     // full[s] @ barb+16s, empty[s] @ barb+16s+8

    const int tid = threadIdx.x, lane = tid & 31, wid = tid >> 5;
    const size_t b = blockIdx.y;
    const int m0 = blockIdx.x * 64;

    // A tiles for this (b, mtile): 64 consecutive 8 KB tiles (kt-major)
    const __nv_bfloat16* Atile = g_A + (((size_t)b * 64 + (m0 >> 6)) * 64) * 4096;
    const __nv_bfloat16* B     = Tin + (size_t)b * NN * DIM;

    if (tid == 0) {
        #pragma unroll
        for (int s = 0; s < STAGES; s++) {
            mbar_init(barb + 16 * s, 1);           // full : expect_tx arrive
            mbar_init(barb + 16 * s + 8, 128);     // empty: 128 consumer threads
        }
    }
    __syncthreads();

    if (wid == 4) {
        // ================= producer (single thread) =================
        if (lane == 0) {
            int st_i = 0, ph = 1;                  // empty-wait cursor (first pass free)
            for (int kt = 0; kt < KT_TOT; kt++) {
                mbar_wait(barb + 16 * st_i + 8, (uint32_t)ph);
                const uint32_t st = base + st_i * STG;
                const uint32_t fb = barb + 16 * st_i;
                mbar_expect_tx(fb, STG);
                bulk_ld(st,          Atile + (size_t)kt * 4096,      A_STG, fb);
                bulk_ld(st + A_STG,  B + (size_t)kt * 64 * DIM,      B_STG, fb);
                if (++st_i == STAGES) { st_i = 0; ph ^= 1; }
            }
        }
        return;
    }

    // ================= consumers =================
    const int wm = wid & 1, wn = wid >> 1;
    const int la = lane & 15, lb = lane >> 4;

    float acc[2][4][4];
    #pragma unroll
    for (int i = 0; i < 2; i++)
        #pragma unroll
        for (int j = 0; j < 4; j++)
            #pragma unroll
            for (int q = 0; q < 4; q++) acc[i][j][q] = 0.f;

    int st_i = 0, ph = 0;
    for (int kt = 0; kt < KT_TOT; kt++) {
        mbar_wait(barb + 16 * st_i, (uint32_t)ph);     // acquire full[s]
        const uint32_t sa = base + st_i * STG;
        const uint32_t sbm = sa + A_STG;

        #pragma unroll
        for (int kk = 0; kk < 64; kk += 16) {
            uint32_t af[2][4];
            #pragma unroll
            for (int mt = 0; mt < 2; mt++) {
                int r = wm * 32 + mt * 16 + la;        // tile row
                int c = (kk >> 3) + lb;                // 16B chunk idx
                uint32_t p = sa + r * 128 + (((c ^ (r & 7)) & 7) << 4);
                asm volatile("ldmatrix.sync.aligned.m8n8.x4.shared.b16 {%0,%1,%2,%3},[%4];\n"
                             : "=r"(af[mt][0]), "=r"(af[mt][1]), "=r"(af[mt][2]), "=r"(af[mt][3])
                             : "r"(p));
            }
            uint32_t bf_[2][4];
            #pragma unroll
            for (int nh = 0; nh < 2; nh++) {
                int r = kk + la;                       // k-local row
                int c = (wn * 32 + nh * 16) / 8 + lb;  // 16B chunk idx
                uint32_t p = sbm + r * 128 + (((c ^ (r & 7)) & 7) << 4);
                asm volatile("ldmatrix.sync.aligned.m8n8.x4.trans.shared.b16 {%0,%1,%2,%3},[%4];\n"
                             : "=r"(bf_[nh][0]), "=r"(bf_[nh][1]), "=r"(bf_[nh][2]), "=r"(bf_[nh][3])
                             : "r"(p));
            }
            #pragma unroll
            for (int mt = 0; mt < 2; mt++)
                #pragma unroll
                for (int nt = 0; nt < 4; nt++) {
                    uint32_t b0 = bf_[nt >> 1][(nt & 1) * 2];
                    uint32_t b1 = bf_[nt >> 1][(nt & 1) * 2 + 1];
                    float* c = acc[mt][nt];
                    asm volatile(
                        "mma.sync.aligned.m16n8k16.row.col.f32.bf16.bf16.f32 "
                        "{%0,%1,%2,%3},{%4,%5,%6,%7},{%8,%9},{%0,%1,%2,%3};\n"
                        : "+f"(c[0]), "+f"(c[1]), "+f"(c[2]), "+f"(c[3])
                        : "r"(af[mt][0]), "r"(af[mt][1]), "r"(af[mt][2]), "r"(af[mt][3]),
                          "r"(b0), "r"(b1));
                }
        }
        mbar_arrive(barb + 16 * st_i + 8);             // release empty[s]
        if (++st_i == STAGES) { st_i = 0; ph ^= 1; }
    }

    // epilogue: S_next[r] = d_r*acc + P[r]; T_next stored with row swizzle
    #pragma unroll
    for (int mt = 0; mt < 2; mt++) {
        const size_t gr0 = b * NN + m0 + wm * 32 + mt * 16 + (lane >> 2);
        const size_t gr1 = gr0 + 8;
        const float d0 = g_deg[gr0], d1 = g_deg[gr1];
        #pragma unroll
        for (int nt = 0; nt < 4; nt++) {
            int c = wn * 32 + nt * 8 + (lane & 3) * 2;
            float2 p0 = *(const float2*)(Padd + gr0 * DIM + c);
            float2 p1 = *(const float2*)(Padd + gr1 * DIM + c);
            float* ac = acc[mt][nt];
            float s00 = d0 * ac[0] + p0.x, s01 = d0 * ac[1] + p0.y;
            float s10 = d1 * ac[2] + p1.x, s11 = d1 * ac[3] + p1.y;
            if (outp) {
                float b0 = bias[c], b1 = bias[c + 1];
                *(float2*)(outp + gr0 * DIM + c) = make_float2(s00 + b0, s01 + b1);
                *(float2*)(outp + gr1 * DIM + c) = make_float2(s10 + b0, s11 + b1);
            } else {
                *(__nv_bfloat162*)(Tout + gr0 * DIM + swz((int)gr0, c)) = __floats2bfloat162_rn(d0 * s00, d0 * s01);
                *(__nv_bfloat162*)(Tout + gr1 * DIM + swz((int)gr1, c)) = __floats2bfloat162_rn(d1 * s10, d1 * s11);
            }
        }
    }
}

// ---------------- launch ----------------
extern "C" void kernel_launch(void* const* d_in, const int* in_sizes, int n_in,
                              void* d_out, int out_size) {
    const float* x     = (const float*)d_in[0];   // [4,4096,64]
    const float* graph = (const float*)d_in[1];   // [4,4096,4096]
    const float* W     = (const float*)d_in[2];   // [64,256]
    const float* bias  = (const float*)d_in[3];   // [64]
    float* out = (float*)d_out;                   // [4,4096,64]

    const int smem_bytes = STAGES * STG + STAGES * 16;    // 98304 + 96 -> 2 CTAs/SM
    static bool attr_set = false;                 // persistent process state, not a work guard
    if (!attr_set) {
        cudaFuncSetAttribute(gemm_kernel, cudaFuncAttributeMaxDynamicSharedMemorySize, smem_bytes);
        attr_set = true;
    }

    prep_kernel<<<NROWS / 8, 256>>>(graph);
    precompute_kernel<<<NROWS / 64, 256>>>(x, W);

    __nv_bfloat16* s0 = nullptr;
    cudaGetSymbolAddress((void**)&s0, g_sbf);     // g_sbf[0]
    __nv_bfloat16* s1 = s0 + (size_t)NROWS * DIM; // g_sbf[1]
    float* P = nullptr;
    cudaGetSymbolAddress((void**)&P, g_P);        // g_P[0]

    dim3 grid(NN / 64, BATCH);                    // 256 CTAs
    gemm_kernel<<<grid, 160, smem_bytes>>>(s0, s1, P + 2 * (size_t)NROWS * DIM, nullptr, bias);
    gemm_kernel<<<grid, 160, smem_bytes>>>(s1, s0, P + 1 * (size_t)NROWS * DIM, nullptr, bias);
    gemm_kernel<<<grid, 160, smem_bytes>>>(s0, s1, P, out, bias);
}